// round 8
// baseline (speedup 1.0000x reference)
#include <cuda_runtime.h>
#include <cuda_bf16.h>
#include <cstdint>

#define IN_FEAT   256
#define OUT_FEAT  32
#define MAXN      102400
#define CAP       64             // bucket slots per row (avg degree 16)
#define MAXOVF    4096
#define TM        256
#define NT        256
#define KCH       32
#define NCHUNK    (IN_FEAT / KCH)
#define SFP       36
#define KP        260
#define SWT_ELEMS (OUT_FEAT * KP)
#define SF_ELEMS  (TM * SFP)
#define SMEM_BYTES ((SWT_ELEMS + 2 * SF_ELEMS) * 4)

__device__ float g_x[MAXN * OUT_FEAT];          // projected features (13 MB)
__device__ int   g_cnt[MAXN];
__device__ uint2 g_bucket[(size_t)MAXN * CAP];  // (col, val_bits) (52 MB)
__device__ int   g_ovf_n;
__device__ int   g_ovf[MAXOVF];

// ---------------------------------------------------------------------------
// helpers
// ---------------------------------------------------------------------------
__device__ __forceinline__ unsigned smem_u32(const void* p) {
    return (unsigned)__cvta_generic_to_shared(p);
}
__device__ __forceinline__ void cp_async16(unsigned dst, const void* src) {
    asm volatile("cp.async.cg.shared.global [%0], [%1], 16;"
                 :: "r"(dst), "l"(src));
}
__device__ __forceinline__ void cp_commit() {
    asm volatile("cp.async.commit_group;");
}
template <int N>
__device__ __forceinline__ void cp_wait() {
    asm volatile("cp.async.wait_group %0;" :: "n"(N));
}
__device__ __forceinline__ unsigned f2tf32(float f) {
    unsigned r;
    asm("cvt.rna.tf32.f32 %0, %1;" : "=r"(r) : "f"(f));
    return r;
}
__device__ __forceinline__ void mma_tf32(float& c0, float& c1, float& c2, float& c3,
                                         unsigned a0, unsigned a1, unsigned a2, unsigned a3,
                                         unsigned b0, unsigned b1) {
    asm volatile("mma.sync.aligned.m16n8k8.row.col.f32.tf32.tf32.f32 "
                 "{%0,%1,%2,%3}, {%4,%5,%6,%7}, {%8,%9}, {%0,%1,%2,%3};"
                 : "+f"(c0), "+f"(c1), "+f"(c2), "+f"(c3)
                 : "r"(a0), "r"(a1), "r"(a2), "r"(a3), "r"(b0), "r"(b1));
}

// ---------------------------------------------------------------------------
// Stage 1: x = feat @ W   (TF32 tensor-core GEMM — unchanged, ~28 us)
// ---------------------------------------------------------------------------
__global__ __launch_bounds__(NT)
void gemm_kernel(const float* __restrict__ feat,
                 const float* __restrict__ weight,
                 int n_nodes) {
    extern __shared__ char smem[];
    unsigned* sWt = (unsigned*)smem;
    float*    sF  = (float*)(smem + SWT_ELEMS * 4);

    const int t    = threadIdx.x;
    const int warp = t >> 5;
    const int lane = t & 31;
    const int gid  = lane >> 2;
    const int tid4 = lane & 3;
    const int row0 = blockIdx.x * TM;

    auto stage = [&](int c, int b) {
        #pragma unroll
        for (int i = 0; i < (TM * 8) / NT; i++) {
            int idx = i * NT + t;
            int r   = idx >> 3;
            int s   = idx & 7;
            int gr  = row0 + r;
            if (gr > n_nodes - 1) gr = n_nodes - 1;
            const float* src = feat + (size_t)gr * IN_FEAT + c * KCH + s * 4;
            cp_async16(smem_u32(&sF[b * SF_ELEMS + r * SFP + s * 4]), src);
        }
        cp_commit();
    };

    stage(0, 0);

    #pragma unroll
    for (int i = 0; i < (IN_FEAT * OUT_FEAT) / NT; i++) {
        int idx = i * NT + t;
        int k = idx >> 5;
        int n = idx & 31;
        sWt[n * KP + k] = f2tf32(weight[idx]);
    }

    float acc[2][4][4];
    #pragma unroll
    for (int m = 0; m < 2; m++)
        #pragma unroll
        for (int n = 0; n < 4; n++)
            #pragma unroll
            for (int i = 0; i < 4; i++) acc[m][n][i] = 0.f;

    #pragma unroll 1
    for (int c = 0; c < NCHUNK; c++) {
        int b = c & 1;
        if (c + 1 < NCHUNK) { stage(c + 1, b ^ 1); cp_wait<1>(); }
        else                { cp_wait<0>(); }
        __syncthreads();

        const float* fb = &sF[b * SF_ELEMS];
        #pragma unroll
        for (int ks = 0; ks < KCH / 8; ks++) {
            int kl = ks * 8;
            int kg = c * KCH + kl;

            unsigned bf[4][2];
            #pragma unroll
            for (int n = 0; n < 4; n++) {
                const unsigned* wp = &sWt[(n * 8 + gid) * KP + kg + tid4];
                bf[n][0] = wp[0];
                bf[n][1] = wp[4];
            }

            unsigned af[2][4];
            #pragma unroll
            for (int m = 0; m < 2; m++) {
                int rb = warp * 32 + m * 16 + gid;
                const float* ap0 = &fb[rb * SFP + kl + tid4];
                const float* ap1 = &fb[(rb + 8) * SFP + kl + tid4];
                af[m][0] = f2tf32(ap0[0]);
                af[m][1] = f2tf32(ap1[0]);
                af[m][2] = f2tf32(ap0[4]);
                af[m][3] = f2tf32(ap1[4]);
            }

            #pragma unroll
            for (int n = 0; n < 4; n++)
                #pragma unroll
                for (int m = 0; m < 2; m++)
                    mma_tf32(acc[m][n][0], acc[m][n][1], acc[m][n][2], acc[m][n][3],
                             af[m][0], af[m][1], af[m][2], af[m][3],
                             bf[n][0], bf[n][1]);
        }
        __syncthreads();
    }

    #pragma unroll
    for (int m = 0; m < 2; m++) {
        int r0 = row0 + warp * 32 + m * 16 + gid;
        #pragma unroll
        for (int n = 0; n < 4; n++) {
            int col = n * 8 + 2 * tid4;
            if (r0 < n_nodes) {
                float2 v = make_float2(acc[m][n][0], acc[m][n][1]);
                *(float2*)(g_x + (size_t)r0 * OUT_FEAT + col) = v;
            }
            if (r0 + 8 < n_nodes) {
                float2 v = make_float2(acc[m][n][2], acc[m][n][3]);
                *(float2*)(g_x + (size_t)(r0 + 8) * OUT_FEAT + col) = v;
            }
        }
    }
}

// ---------------------------------------------------------------------------
// Stage 2a: counter reset
// ---------------------------------------------------------------------------
__global__ void zero_kernel(int n) {
    int i = blockIdx.x * 256 + threadIdx.x;
    if (i < n) g_cnt[i] = 0;
    if (i == 0) g_ovf_n = 0;
}

// ---------------------------------------------------------------------------
// Stage 2b: bucketize, 4 independent edges per thread (MLP 4)
// ---------------------------------------------------------------------------
__global__ __launch_bounds__(256)
void scatter_kernel(const float* __restrict__ vals,
                    const int* __restrict__ erow,
                    const int* __restrict__ ecol,
                    int n_edges) {
    int base = blockIdx.x * 1024 + threadIdx.x;

    int   r[4], c[4];
    float v[4];
    bool  ok[4];
    #pragma unroll
    for (int i = 0; i < 4; i++) {
        int e = base + i * 256;
        ok[i] = (e < n_edges);
        if (ok[i]) {
            r[i] = __ldg(erow + e);
            c[i] = __ldg(ecol + e);
            v[i] = __ldg(vals + e);
        }
    }
    int pos[4];
    #pragma unroll
    for (int i = 0; i < 4; i++)
        if (ok[i]) pos[i] = atomicAdd(&g_cnt[r[i]], 1);
    #pragma unroll
    for (int i = 0; i < 4; i++) {
        if (!ok[i]) continue;
        if (pos[i] < CAP) {
            g_bucket[(size_t)r[i] * CAP + pos[i]] =
                make_uint2((unsigned)c[i], __float_as_uint(v[i]));
        } else {
            int o = atomicAdd(&g_ovf_n, 1);
            if (o < MAXOVF) g_ovf[o] = base + i * 256;
        }
    }
}

// ---------------------------------------------------------------------------
// Stage 2c: 8 threads/row, 4 cols each; 8-edge batches for deep MLP.
// Pair loads are group-redundant (L1 broadcast) but front-batched, then
// 8 independent float4 x-gathers per exposure.
// ---------------------------------------------------------------------------
__global__ __launch_bounds__(256)
void gather_kernel(float* __restrict__ out, int n_nodes) {
    int idx = blockIdx.x * 256 + threadIdx.x;
    int row = idx >> 3;
    if (row >= n_nodes) return;
    int q = (idx & 7) << 2;

    int cnt = g_cnt[row];
    if (cnt > CAP) cnt = CAP;
    const uint2* bk = g_bucket + (size_t)row * CAP;

    float4 acc; acc.x = acc.y = acc.z = acc.w = 0.f;

    int j = 0;
    for (; j + 8 <= cnt; j += 8) {
        uint2 p[8];
        #pragma unroll
        for (int u = 0; u < 8; u++) p[u] = bk[j + u];
        float4 xv[8];
        #pragma unroll
        for (int u = 0; u < 8; u++)
            xv[u] = *(const float4*)(g_x + (size_t)p[u].x * OUT_FEAT + q);
        #pragma unroll
        for (int u = 0; u < 8; u++) {
            float v = __uint_as_float(p[u].y);
            acc.x += v * xv[u].x; acc.y += v * xv[u].y;
            acc.z += v * xv[u].z; acc.w += v * xv[u].w;
        }
    }
    if (j + 4 <= cnt) {
        uint2 p[4];
        #pragma unroll
        for (int u = 0; u < 4; u++) p[u] = bk[j + u];
        float4 xv[4];
        #pragma unroll
        for (int u = 0; u < 4; u++)
            xv[u] = *(const float4*)(g_x + (size_t)p[u].x * OUT_FEAT + q);
        #pragma unroll
        for (int u = 0; u < 4; u++) {
            float v = __uint_as_float(p[u].y);
            acc.x += v * xv[u].x; acc.y += v * xv[u].y;
            acc.z += v * xv[u].z; acc.w += v * xv[u].w;
        }
        j += 4;
    }
    for (; j < cnt; j++) {
        uint2 p = bk[j];
        float4 xv = *(const float4*)(g_x + (size_t)p.x * OUT_FEAT + q);
        float v = __uint_as_float(p.y);
        acc.x += v * xv.x; acc.y += v * xv.y;
        acc.z += v * xv.z; acc.w += v * xv.w;
    }

    *(float4*)(out + (size_t)row * OUT_FEAT + q) = acc;
}

// ---------------------------------------------------------------------------
// Stage 2d: overflow fixup (expected empty; unconditional correctness)
// ---------------------------------------------------------------------------
__global__ void fixup_kernel(const float* __restrict__ vals,
                             const int* __restrict__ erow,
                             const int* __restrict__ ecol,
                             float* __restrict__ out) {
    int n = g_ovf_n;
    if (n > MAXOVF) n = MAXOVF;
    for (int i = threadIdx.x; i < n * 8; i += 256) {
        int e = g_ovf[i >> 3];
        int q = (i & 7) << 2;
        int r = erow[e], c = ecol[e];
        float v = vals[e];
        #pragma unroll
        for (int k = 0; k < 4; k++)
            atomicAdd(&out[(size_t)r * OUT_FEAT + q + k],
                      v * g_x[(size_t)c * OUT_FEAT + q + k]);
    }
}

// ---------------------------------------------------------------------------
extern "C" void kernel_launch(void* const* d_in, const int* in_sizes, int n_in,
                              void* d_out, int out_size) {
    const float* feat   = (const float*)d_in[0];
    const float* weight = (const float*)d_in[1];
    const float* vals   = (const float*)d_in[2];
    const int*   erow   = (const int*)d_in[3];
    const int*   ecol   = (const int*)d_in[4];
    float* out = (float*)d_out;

    int n_nodes = in_sizes[0] / IN_FEAT;
    int n_edges = in_sizes[2];

    static cudaStream_t s2 = nullptr;
    static cudaEvent_t  evFork = nullptr, evJoin = nullptr;
    if (!s2) {
        cudaStreamCreateWithFlags(&s2, cudaStreamNonBlocking);
        cudaEventCreateWithFlags(&evFork, cudaEventDisableTiming);
        cudaEventCreateWithFlags(&evJoin, cudaEventDisableTiming);
    }

    cudaFuncSetAttribute(gemm_kernel,
                         cudaFuncAttributeMaxDynamicSharedMemorySize, SMEM_BYTES);

    int nb_nodes = (n_nodes + 255) / 256;
    int nb_edges4 = (n_edges + 1023) / 1024;
    int gemm_blocks = (n_nodes + TM - 1) / TM;

    // fork: bucket build on s2 overlaps gemm's wave drain
    cudaEventRecord(evFork, 0);
    cudaStreamWaitEvent(s2, evFork, 0);

    gemm_kernel<<<gemm_blocks, NT, SMEM_BYTES>>>(feat, weight, n_nodes);

    zero_kernel<<<nb_nodes, 256, 0, s2>>>(n_nodes);
    scatter_kernel<<<nb_edges4, 256, 0, s2>>>(vals, erow, ecol, n_edges);

    cudaEventRecord(evJoin, s2);
    cudaStreamWaitEvent(0, evJoin, 0);

    long long gw = (long long)n_nodes * 8;
    int nb_gather = (int)((gw + 255) / 256);
    gather_kernel<<<nb_gather, 256>>>(out, n_nodes);

    fixup_kernel<<<1, 256>>>(vals, erow, ecol, out);
}

// round 9
// speedup vs baseline: 1.0096x; 1.0096x over previous
#include <cuda_runtime.h>
#include <cuda_bf16.h>
#include <cstdint>

#define IN_FEAT   256
#define OUT_FEAT  32
#define MAXN      102400
#define CAP       32             // bucket slots per row (avg degree 16)
#define MAXOVF    8192
#define TM        256
#define NT        256
#define KCH       16             // k-floats per staged chunk (64 B per row)
#define NCHUNK    (IN_FEAT / KCH)
#define SFP       20             // padded floats per staged row
#define KP        260
#define SWT_ELEMS (OUT_FEAT * KP)
#define SF_ELEMS  (TM * SFP)
#define SMEM_BYTES ((SWT_ELEMS + 2 * SF_ELEMS) * 4)   // 72.5 KB -> 3 blocks/SM

__device__ float g_x[MAXN * OUT_FEAT];          // projected features (13 MB)
__device__ int   g_cnt[MAXN];
__device__ uint2 g_bucket[(size_t)MAXN * CAP];  // (col, val_bits) (25.6 MB)
__device__ int   g_ovf_n;
__device__ int   g_ovf[MAXOVF];

// ---------------------------------------------------------------------------
// helpers
// ---------------------------------------------------------------------------
__device__ __forceinline__ unsigned smem_u32(const void* p) {
    return (unsigned)__cvta_generic_to_shared(p);
}
__device__ __forceinline__ void cp_async16(unsigned dst, const void* src) {
    asm volatile("cp.async.cg.shared.global [%0], [%1], 16;"
                 :: "r"(dst), "l"(src));
}
__device__ __forceinline__ void cp_commit() {
    asm volatile("cp.async.commit_group;");
}
template <int N>
__device__ __forceinline__ void cp_wait() {
    asm volatile("cp.async.wait_group %0;" :: "n"(N));
}
__device__ __forceinline__ unsigned f2tf32(float f) {
    unsigned r;
    asm("cvt.rna.tf32.f32 %0, %1;" : "=r"(r) : "f"(f));
    return r;
}
__device__ __forceinline__ void mma_tf32(float& c0, float& c1, float& c2, float& c3,
                                         unsigned a0, unsigned a1, unsigned a2, unsigned a3,
                                         unsigned b0, unsigned b1) {
    asm volatile("mma.sync.aligned.m16n8k8.row.col.f32.tf32.tf32.f32 "
                 "{%0,%1,%2,%3}, {%4,%5,%6,%7}, {%8,%9}, {%0,%1,%2,%3};"
                 : "+f"(c0), "+f"(c1), "+f"(c2), "+f"(c3)
                 : "r"(a0), "r"(a1), "r"(a2), "r"(a3), "r"(b0), "r"(b1));
}

// ---------------------------------------------------------------------------
// Stage 1: x = feat @ W  (TF32 MMA; 72.5 KB smem -> 3 blocks/SM, ONE wave)
// ---------------------------------------------------------------------------
__global__ __launch_bounds__(NT)
void gemm_kernel(const float* __restrict__ feat,
                 const float* __restrict__ weight,
                 int n_nodes) {
    extern __shared__ char smem[];
    unsigned* sWt = (unsigned*)smem;
    float*    sF  = (float*)(smem + SWT_ELEMS * 4);

    const int t    = threadIdx.x;
    const int warp = t >> 5;
    const int lane = t & 31;
    const int gid  = lane >> 2;
    const int tid4 = lane & 3;
    const int row0 = blockIdx.x * TM;

    // stage chunk c (KCH=16 floats per row): TM*4 16B segments
    auto stage = [&](int c, int b) {
        #pragma unroll
        for (int i = 0; i < (TM * 4) / NT; i++) {
            int idx = i * NT + t;               // 0..1023
            int r   = idx >> 2;                 // local row
            int s   = idx & 3;                  // 16B segment
            int gr  = row0 + r;
            if (gr > n_nodes - 1) gr = n_nodes - 1;
            const float* src = feat + (size_t)gr * IN_FEAT + c * KCH + s * 4;
            cp_async16(smem_u32(&sF[b * SF_ELEMS + r * SFP + s * 4]), src);
        }
        cp_commit();
    };

    stage(0, 0);

    #pragma unroll
    for (int i = 0; i < (IN_FEAT * OUT_FEAT) / NT; i++) {
        int idx = i * NT + t;
        int k = idx >> 5;
        int n = idx & 31;
        sWt[n * KP + k] = f2tf32(weight[idx]);
    }

    float acc[2][4][4];
    #pragma unroll
    for (int m = 0; m < 2; m++)
        #pragma unroll
        for (int n = 0; n < 4; n++)
            #pragma unroll
            for (int i = 0; i < 4; i++) acc[m][n][i] = 0.f;

    #pragma unroll 1
    for (int c = 0; c < NCHUNK; c++) {
        int b = c & 1;
        if (c + 1 < NCHUNK) { stage(c + 1, b ^ 1); cp_wait<1>(); }
        else                { cp_wait<0>(); }
        __syncthreads();

        const float* fb = &sF[b * SF_ELEMS];
        #pragma unroll
        for (int ks = 0; ks < KCH / 8; ks++) {
            int kl = ks * 8;
            int kg = c * KCH + kl;

            unsigned bf[4][2];
            #pragma unroll
            for (int n = 0; n < 4; n++) {
                const unsigned* wp = &sWt[(n * 8 + gid) * KP + kg + tid4];
                bf[n][0] = wp[0];
                bf[n][1] = wp[4];
            }

            unsigned af[2][4];
            #pragma unroll
            for (int m = 0; m < 2; m++) {
                int rb = warp * 32 + m * 16 + gid;
                const float* ap0 = &fb[rb * SFP + kl + tid4];
                const float* ap1 = &fb[(rb + 8) * SFP + kl + tid4];
                af[m][0] = f2tf32(ap0[0]);
                af[m][1] = f2tf32(ap1[0]);
                af[m][2] = f2tf32(ap0[4]);
                af[m][3] = f2tf32(ap1[4]);
            }

            #pragma unroll
            for (int n = 0; n < 4; n++)
                #pragma unroll
                for (int m = 0; m < 2; m++)
                    mma_tf32(acc[m][n][0], acc[m][n][1], acc[m][n][2], acc[m][n][3],
                             af[m][0], af[m][1], af[m][2], af[m][3],
                             bf[n][0], bf[n][1]);
        }
        __syncthreads();
    }

    #pragma unroll
    for (int m = 0; m < 2; m++) {
        int r0 = row0 + warp * 32 + m * 16 + gid;
        #pragma unroll
        for (int n = 0; n < 4; n++) {
            int col = n * 8 + 2 * tid4;
            if (r0 < n_nodes) {
                float2 v = make_float2(acc[m][n][0], acc[m][n][1]);
                *(float2*)(g_x + (size_t)r0 * OUT_FEAT + col) = v;
            }
            if (r0 + 8 < n_nodes) {
                float2 v = make_float2(acc[m][n][2], acc[m][n][3]);
                *(float2*)(g_x + (size_t)(r0 + 8) * OUT_FEAT + col) = v;
            }
        }
    }
}

// ---------------------------------------------------------------------------
// Stage 2a: counter reset
// ---------------------------------------------------------------------------
__global__ void zero_kernel(int n) {
    int i = blockIdx.x * 256 + threadIdx.x;
    if (i < n) g_cnt[i] = 0;
    if (i == 0) g_ovf_n = 0;
}

// ---------------------------------------------------------------------------
// Stage 2b: bucketize (simple 1-edge form — R7's 4-edge batch regressed)
// ---------------------------------------------------------------------------
__global__ __launch_bounds__(256)
void scatter_kernel(const float* __restrict__ vals,
                    const int* __restrict__ erow,
                    const int* __restrict__ ecol,
                    int n_edges) {
    int e = blockIdx.x * 256 + threadIdx.x;
    if (e >= n_edges) return;
    int r = __ldg(erow + e);
    int c = __ldg(ecol + e);
    float v = __ldg(vals + e);
    int pos = atomicAdd(&g_cnt[r], 1);
    if (pos < CAP) {
        g_bucket[(size_t)r * CAP + pos] =
            make_uint2((unsigned)c, __float_as_uint(v));
    } else {
        int o = atomicAdd(&g_ovf_n, 1);
        if (o < MAXOVF) g_ovf[o] = e;
    }
}

// ---------------------------------------------------------------------------
// Stage 2c: 4 threads/row, 8 cols each; 4-edge batch = 4 pair loads + 8
// independent LDG.128 in flight.  launch_bounds(256,2) gives ptxas the
// register budget to actually keep the batch live (R8 failure mode).
// ---------------------------------------------------------------------------
__global__ __launch_bounds__(256, 2)
void gather_kernel(float* __restrict__ out, int n_nodes) {
    int idx = blockIdx.x * 256 + threadIdx.x;
    int row = idx >> 2;
    if (row >= n_nodes) return;
    int q = (idx & 3) << 3;          // float col offset: 0,8,16,24

    int cnt = g_cnt[row];
    if (cnt > CAP) cnt = CAP;
    const uint2* bk = g_bucket + (size_t)row * CAP;

    float4 a0; a0.x = a0.y = a0.z = a0.w = 0.f;
    float4 a1; a1.x = a1.y = a1.z = a1.w = 0.f;

    int j = 0;
    for (; j + 4 <= cnt; j += 4) {
        uint2 p[4];
        #pragma unroll
        for (int u = 0; u < 4; u++) p[u] = bk[j + u];
        float4 xa[4], xb[4];
        #pragma unroll
        for (int u = 0; u < 4; u++) {
            const float* xp = g_x + (size_t)p[u].x * OUT_FEAT + q;
            xa[u] = *(const float4*)xp;
            xb[u] = *(const float4*)(xp + 4);
        }
        #pragma unroll
        for (int u = 0; u < 4; u++) {
            float v = __uint_as_float(p[u].y);
            a0.x += v * xa[u].x; a0.y += v * xa[u].y;
            a0.z += v * xa[u].z; a0.w += v * xa[u].w;
            a1.x += v * xb[u].x; a1.y += v * xb[u].y;
            a1.z += v * xb[u].z; a1.w += v * xb[u].w;
        }
    }
    for (; j < cnt; j++) {
        uint2 p = bk[j];
        const float* xp = g_x + (size_t)p.x * OUT_FEAT + q;
        float4 xa = *(const float4*)xp;
        float4 xb = *(const float4*)(xp + 4);
        float v = __uint_as_float(p.y);
        a0.x += v * xa.x; a0.y += v * xa.y; a0.z += v * xa.z; a0.w += v * xa.w;
        a1.x += v * xb.x; a1.y += v * xb.y; a1.z += v * xb.z; a1.w += v * xb.w;
    }

    float* op = out + (size_t)row * OUT_FEAT + q;
    *(float4*)op       = a0;
    *(float4*)(op + 4) = a1;
}

// ---------------------------------------------------------------------------
// Stage 2d: overflow fixup (expected ~30 edges at CAP=32; unconditional)
// ---------------------------------------------------------------------------
__global__ void fixup_kernel(const float* __restrict__ vals,
                             const int* __restrict__ erow,
                             const int* __restrict__ ecol,
                             float* __restrict__ out) {
    int n = g_ovf_n;
    if (n > MAXOVF) n = MAXOVF;
    for (int i = threadIdx.x; i < n * 8; i += 256) {
        int e = g_ovf[i >> 3];
        int q = (i & 7) << 2;
        int r = erow[e], c = ecol[e];
        float v = vals[e];
        #pragma unroll
        for (int k = 0; k < 4; k++)
            atomicAdd(&out[(size_t)r * OUT_FEAT + q + k],
                      v * g_x[(size_t)c * OUT_FEAT + q + k]);
    }
}

// ---------------------------------------------------------------------------
extern "C" void kernel_launch(void* const* d_in, const int* in_sizes, int n_in,
                              void* d_out, int out_size) {
    const float* feat   = (const float*)d_in[0];
    const float* weight = (const float*)d_in[1];
    const float* vals   = (const float*)d_in[2];
    const int*   erow   = (const int*)d_in[3];
    const int*   ecol   = (const int*)d_in[4];
    float* out = (float*)d_out;

    int n_nodes = in_sizes[0] / IN_FEAT;
    int n_edges = in_sizes[2];

    static cudaStream_t s2 = nullptr;
    static cudaEvent_t  evFork = nullptr, evJoin = nullptr;
    if (!s2) {
        cudaStreamCreateWithFlags(&s2, cudaStreamNonBlocking);
        cudaEventCreateWithFlags(&evFork, cudaEventDisableTiming);
        cudaEventCreateWithFlags(&evJoin, cudaEventDisableTiming);
    }

    cudaFuncSetAttribute(gemm_kernel,
                         cudaFuncAttributeMaxDynamicSharedMemorySize, SMEM_BYTES);

    int nb_nodes = (n_nodes + 255) / 256;
    int nb_edges = (n_edges + 255) / 256;
    int gemm_blocks = (n_nodes + TM - 1) / TM;

    // fork: bucket build on s2 co-runs with the (now single-wave) gemm
    cudaEventRecord(evFork, 0);
    cudaStreamWaitEvent(s2, evFork, 0);

    gemm_kernel<<<gemm_blocks, NT, SMEM_BYTES>>>(feat, weight, n_nodes);

    zero_kernel<<<nb_nodes, 256, 0, s2>>>(n_nodes);
    scatter_kernel<<<nb_edges, 256, 0, s2>>>(vals, erow, ecol, n_edges);

    cudaEventRecord(evJoin, s2);
    cudaStreamWaitEvent(0, evJoin, 0);

    long long gw = (long long)n_nodes * 4;
    int nb_gather = (int)((gw + 255) / 256);
    gather_kernel<<<nb_gather, 256>>>(out, n_nodes);

    fixup_kernel<<<1, 256>>>(vals, erow, ecol, out);
}